// round 5
// baseline (speedup 1.0000x reference)
#include <cuda_runtime.h>

#define LQ  2048
#define SK  2048
#define NB  4
#define EMB 512
#define NH  16
#define HD  32
#define ROWS (LQ * NB)   // 8192

// Scratch (allocation-free rule: __device__ globals)
__device__ float g_Q[NB * NH * LQ * HD];   // [n,h,l,d]
__device__ float g_K[NB * NH * SK * HD];   // [n,h,s,d]
__device__ float g_V[NB * NH * SK * HD];
__device__ float g_O[ROWS * EMB];          // attention output, (l*NB+n, e) row-major

// ---------------------------------------------------------------------------
// tf32 helpers
// ---------------------------------------------------------------------------
__device__ __forceinline__ unsigned f2tf(float x) {
    unsigned r;
    asm("cvt.rna.tf32.f32 %0, %1;" : "=r"(r) : "f"(x));
    return r;
}
__device__ __forceinline__ float tf32f(float x) {
    return __uint_as_float(f2tf(x));
}
__device__ __forceinline__ void mma_tf32(float* c, const unsigned* a,
                                         unsigned b0, unsigned b1) {
    asm volatile(
        "mma.sync.aligned.m16n8k8.row.col.f32.tf32.tf32.f32 "
        "{%0,%1,%2,%3}, {%4,%5,%6,%7}, {%8,%9}, {%0,%1,%2,%3};"
        : "+f"(c[0]), "+f"(c[1]), "+f"(c[2]), "+f"(c[3])
        : "r"(a[0]), "r"(a[1]), "r"(a[2]), "r"(a[3]), "r"(b0), "r"(b1));
}

// ---------------------------------------------------------------------------
// 3xTF32 tensor-core GEMM: out[r,f] = sum_e A[r,e] * W[f,e] + bias[f]
// Block tile 256x128, BK=16, 256 threads = 8 warps (4 along M x 2 along N),
// warptile 64x64 (mi=4, ni=8). Smem holds hi/lo tiles in a permuted
// fragment-native layout: a-frags load as one LDS.128, b-frags as LDS.64.
// ---------------------------------------------------------------------------
template<int MODE>
__global__ __launch_bounds__(256)
void gemm_mma_kernel(const float* __restrict__ Aq, const float* __restrict__ Ak,
                     const float* __restrict__ Av, const float* __restrict__ Wfull,
                     const float* __restrict__ bfull, float* __restrict__ outp)
{
    // A: 16 m-groups x 2 kb x 32 lanes x float4  = 4096 floats (16KB) each
    // B:  16 n-groups x 2 kb x 32 lanes x float2 = 2048 floats (8KB)  each
    __shared__ float Ah_s[4096];
    __shared__ float Al_s[4096];
    __shared__ float Bh_s[2048];
    __shared__ float Bl_s[2048];

    const int tid    = threadIdx.x;
    const int warp   = tid >> 5;
    const int lane   = tid & 31;
    const int g      = lane >> 2;
    const int t      = lane & 3;
    const int warp_m = warp >> 1;   // 0..3
    const int warp_n = warp & 1;    // 0..1
    const int r0     = blockIdx.x * 256;
    const int f0     = blockIdx.y * 128;

    const float* A;
    const float* W;
    const float* bias;
    if (MODE == 0) {
        const int z = blockIdx.z;
        A    = (z == 0) ? Aq : (z == 1) ? Ak : Av;
        W    = Wfull + z * EMB * EMB;
        bias = bfull + z * EMB;
    } else {
        A    = g_O;
        W    = Wfull;
        bias = bfull;
    }

    const int rowBase = tid >> 2;          // 0..63
    const int kkL     = (tid & 3) << 2;    // 0,4,8,12

    float acc[4][8][4];
    #pragma unroll
    for (int mi = 0; mi < 4; mi++)
        #pragma unroll
        for (int ni = 0; ni < 8; ni++)
            #pragma unroll
            for (int j = 0; j < 4; j++) acc[mi][ni][j] = 0.f;

    // initial global prefetch
    float4 aReg[4], bReg[2];
    #pragma unroll
    for (int i = 0; i < 4; i++)
        aReg[i] = *(const float4*)(A + (size_t)(r0 + rowBase + i * 64) * EMB + kkL);
    #pragma unroll
    for (int i = 0; i < 2; i++)
        bReg[i] = *(const float4*)(W + (size_t)(f0 + rowBase + i * 64) * EMB + kkL);

    for (int k0 = 0; k0 < EMB; k0 += 16) {
        // ---- store prefetched tile to smem (permuted, hi/lo split) ----
        #pragma unroll
        for (int i = 0; i < 4; i++) {
            const int r  = rowBase + i * 64;
            const int mt = r >> 4;
            const int gg = r & 15;
            const float x[4] = {aReg[i].x, aReg[i].y, aReg[i].z, aReg[i].w};
            #pragma unroll
            for (int j = 0; j < 4; j++) {
                const int c  = kkL + j;
                const int kb = c >> 3;
                const int cc = c & 7;
                const int off = (((mt * 2 + kb) * 32) + ((gg & 7) * 4 + (cc & 3))) * 4
                                + ((cc >> 2) * 2 + (gg >> 3));
                const float h = tf32f(x[j]);
                Ah_s[off] = h;
                Al_s[off] = tf32f(x[j] - h);
            }
        }
        #pragma unroll
        for (int i = 0; i < 2; i++) {
            const int n  = rowBase + i * 64;
            const int nt = n >> 3;
            const int gb = n & 7;
            const float x[4] = {bReg[i].x, bReg[i].y, bReg[i].z, bReg[i].w};
            #pragma unroll
            for (int j = 0; j < 4; j++) {
                const int c  = kkL + j;
                const int kb = c >> 3;
                const int cc = c & 7;
                const int off = (((nt * 2 + kb) * 32) + (gb * 4 + (cc & 3))) * 2
                                + (cc >> 2);
                const float h = tf32f(x[j]);
                Bh_s[off] = h;
                Bl_s[off] = tf32f(x[j] - h);
            }
        }
        __syncthreads();

        // ---- issue next global loads (overlap with compute) ----
        if (k0 + 16 < EMB) {
            #pragma unroll
            for (int i = 0; i < 4; i++)
                aReg[i] = *(const float4*)(A + (size_t)(r0 + rowBase + i * 64) * EMB + k0 + 16 + kkL);
            #pragma unroll
            for (int i = 0; i < 2; i++)
                bReg[i] = *(const float4*)(W + (size_t)(f0 + rowBase + i * 64) * EMB + k0 + 16 + kkL);
        }

        // ---- compute ----
        #pragma unroll
        for (int kb = 0; kb < 2; kb++) {
            unsigned ah[4][4], al[4][4];
            #pragma unroll
            for (int mi = 0; mi < 4; mi++) {
                const int base = (((warp_m * 4 + mi) * 2 + kb) * 32 + lane) * 4;
                const float4 fh = *(const float4*)(Ah_s + base);
                const float4 fl = *(const float4*)(Al_s + base);
                ah[mi][0] = __float_as_uint(fh.x);
                ah[mi][1] = __float_as_uint(fh.y);
                ah[mi][2] = __float_as_uint(fh.z);
                ah[mi][3] = __float_as_uint(fh.w);
                al[mi][0] = __float_as_uint(fl.x);
                al[mi][1] = __float_as_uint(fl.y);
                al[mi][2] = __float_as_uint(fl.z);
                al[mi][3] = __float_as_uint(fl.w);
            }
            #pragma unroll
            for (int ni = 0; ni < 8; ni++) {
                const int baseB = (((warp_n * 8 + ni) * 2 + kb) * 32 + lane) * 2;
                const float2 bh = *(const float2*)(Bh_s + baseB);
                const float2 bl = *(const float2*)(Bl_s + baseB);
                const unsigned bh0 = __float_as_uint(bh.x);
                const unsigned bh1 = __float_as_uint(bh.y);
                const unsigned bl0 = __float_as_uint(bl.x);
                const unsigned bl1 = __float_as_uint(bl.y);
                #pragma unroll
                for (int mi = 0; mi < 4; mi++) {
                    mma_tf32(acc[mi][ni], ah[mi], bh0, bh1);
                    mma_tf32(acc[mi][ni], ah[mi], bl0, bl1);
                    mma_tf32(acc[mi][ni], al[mi], bh0, bh1);
                }
            }
        }
        __syncthreads();
    }

    // ---- epilogue: c0=(g,2t) c1=(g,2t+1) c2=(g+8,2t) c3=(g+8,2t+1) ----
    #pragma unroll
    for (int mi = 0; mi < 4; mi++) {
        const int rA = r0 + warp_m * 64 + mi * 16 + g;
        const int rB = rA + 8;
        #pragma unroll
        for (int ni = 0; ni < 8; ni++) {
            const float* c = acc[mi][ni];
            const int f  = f0 + warp_n * 64 + ni * 8 + 2 * t;
            const float b0 = bias[f];
            const float b1 = bias[f + 1];
            if (MODE == 0) {
                float* dst = (blockIdx.z == 0) ? g_Q : (blockIdx.z == 1) ? g_K : g_V;
                const int h = f >> 5;
                const int d = f & 31;
                {
                    const int l = rA >> 2, n = rA & 3;
                    *(float2*)(dst + ((size_t)(n * NH + h) * LQ + l) * HD + d) =
                        make_float2(c[0] + b0, c[1] + b1);
                }
                {
                    const int l = rB >> 2, n = rB & 3;
                    *(float2*)(dst + ((size_t)(n * NH + h) * LQ + l) * HD + d) =
                        make_float2(c[2] + b0, c[3] + b1);
                }
            } else {
                *(float2*)(outp + (size_t)rA * EMB + f) = make_float2(c[0] + b0, c[1] + b1);
                *(float2*)(outp + (size_t)rB * EMB + f) = make_float2(c[2] + b0, c[3] + b1);
            }
        }
    }
}

// ---------------------------------------------------------------------------
// LayerNorm over D=32 for K and V (one warp per row)
// ---------------------------------------------------------------------------
__global__ __launch_bounds__(256)
void ln_kernel(const float* __restrict__ w, const float* __restrict__ b)
{
    const int gw   = (blockIdx.x * blockDim.x + threadIdx.x) >> 5;
    const int lane = threadIdx.x & 31;
    const int R    = NB * NH * SK;
    if (gw >= 2 * R) return;
    float* X      = (gw < R) ? g_K : g_V;
    const int row = (gw < R) ? gw : gw - R;

    float x = X[(size_t)row * HD + lane];
    float s = x;
    #pragma unroll
    for (int o = 16; o; o >>= 1) s += __shfl_xor_sync(0xffffffffu, s, o);
    const float mu = s * (1.0f / HD);
    const float dv = x - mu;
    float vv = dv * dv;
    #pragma unroll
    for (int o = 16; o; o >>= 1) vv += __shfl_xor_sync(0xffffffffu, vv, o);
    const float inv = rsqrtf(vv * (1.0f / HD) + 1e-5f);
    X[(size_t)row * HD + lane] = dv * inv * w[lane] + b[lane];
}

// ---------------------------------------------------------------------------
// Flash attention, tf32 mma.sync, 3xTF32-compensated QK, single-tf32 PV.
// Block 128 thr (4 warps); each warp 32 q rows (mi=2); block = 128 q rows.
// S-chunks of 32; K (hi/lo) and V stored in fragment-native permuted smem.
// Q pre-scaled by beta*log2(e); softmax in exp2 domain.
// ---------------------------------------------------------------------------
__global__ __launch_bounds__(128)
void attn_mma_kernel(const float* __restrict__ scaling)
{
    __shared__ float Khs[1024];   // [(nd*4+ks)*32+lane]*2+comp
    __shared__ float Kls[1024];
    __shared__ float Vvs[1024];   // [(kst*4+nd)*32+lane]*2+comp

    const int tid  = threadIdx.x;
    const int warp = tid >> 5;
    const int lane = tid & 31;
    const int g    = lane >> 2;
    const int t    = lane & 3;
    const int nh   = blockIdx.y;   // n*NH + h
    const int h    = nh & (NH - 1);
    const float betaL = scaling[h] * 1.4426950408889634f;
    const int q0   = blockIdx.x * 128 + warp * 32;

    // Q fragments: rows q0 + mi*16 + {g, g+8}, cols ks*8 + {t, t+4}; hi/lo split
    const float* Qp = g_Q + ((size_t)nh * LQ + q0) * HD;
    unsigned aqh[2][4][4], aql[2][4][4];
    #pragma unroll
    for (int mi = 0; mi < 2; mi++) {
        #pragma unroll
        for (int ks = 0; ks < 4; ks++) {
            const float q00 = Qp[(size_t)(mi * 16 + g)     * HD + ks * 8 + t]     * betaL;
            const float q10 = Qp[(size_t)(mi * 16 + g + 8) * HD + ks * 8 + t]     * betaL;
            const float q01 = Qp[(size_t)(mi * 16 + g)     * HD + ks * 8 + t + 4] * betaL;
            const float q11 = Qp[(size_t)(mi * 16 + g + 8) * HD + ks * 8 + t + 4] * betaL;
            aqh[mi][ks][0] = f2tf(q00);
            aqh[mi][ks][1] = f2tf(q10);
            aqh[mi][ks][2] = f2tf(q01);
            aqh[mi][ks][3] = f2tf(q11);
            aql[mi][ks][0] = f2tf(q00 - __uint_as_float(aqh[mi][ks][0]));
            aql[mi][ks][1] = f2tf(q10 - __uint_as_float(aqh[mi][ks][1]));
            aql[mi][ks][2] = f2tf(q01 - __uint_as_float(aqh[mi][ks][2]));
            aql[mi][ks][3] = f2tf(q11 - __uint_as_float(aqh[mi][ks][3]));
        }
    }

    float m[2][2], l[2][2], o[2][4][4];
    #pragma unroll
    for (int mi = 0; mi < 2; mi++) {
        m[mi][0] = m[mi][1] = -1e30f;
        l[mi][0] = l[mi][1] = 0.f;
        #pragma unroll
        for (int nd = 0; nd < 4; nd++)
            #pragma unroll
            for (int j = 0; j < 4; j++) o[mi][nd][j] = 0.f;
    }

    const float* Kb = g_K + (size_t)nh * SK * HD;
    const float* Vb = g_V + (size_t)nh * SK * HD;
    const int sRow = tid >> 3;          // 0..15
    const int dCol = (tid & 7) << 2;    // 0,4,...,28

    for (int s0 = 0; s0 < SK; s0 += 32) {
        // ---- cooperative load: 32x32 K (hi/lo) + V into permuted smem ----
        #pragma unroll
        for (int i = 0; i < 2; i++) {
            const int s = sRow + i * 16;
            const int ndK = s >> 3, gK = s & 7;
            const float4 kv = *(const float4*)(Kb + (size_t)(s0 + s) * HD + dCol);
            const float kx[4] = {kv.x, kv.y, kv.z, kv.w};
            #pragma unroll
            for (int j = 0; j < 4; j++) {
                const int d = dCol + j;
                const int ks_ = d >> 3, cc = d & 7;
                const int off = ((ndK * 4 + ks_) * 32 + gK * 4 + (cc & 3)) * 2 + (cc >> 2);
                const float hh = tf32f(kx[j]);
                Khs[off] = hh;
                Kls[off] = tf32f(kx[j] - hh);
            }
            const int kstV = s >> 3, ssV = s & 7;
            const int tV = ssV & 3, compV = ssV >> 2;
            const float4 vv = *(const float4*)(Vb + (size_t)(s0 + s) * HD + dCol);
            const float vx[4] = {vv.x, vv.y, vv.z, vv.w};
            #pragma unroll
            for (int j = 0; j < 4; j++) {
                const int d = dCol + j;
                const int ndV = d >> 3, gV = d & 7;
                Vvs[((kstV * 4 + ndV) * 32 + gV * 4 + tV) * 2 + compV] = tf32f(vx[j]);
            }
        }
        __syncthreads();

        // ---- QK scores (3xTF32) ----
        float sc[2][4][4];
        #pragma unroll
        for (int mi = 0; mi < 2; mi++)
            #pragma unroll
            for (int nd = 0; nd < 4; nd++)
                #pragma unroll
                for (int j = 0; j < 4; j++) sc[mi][nd][j] = 0.f;

        #pragma unroll
        for (int nd = 0; nd < 4; nd++) {
            #pragma unroll
            for (int ks = 0; ks < 4; ks++) {
                const int baseK = ((nd * 4 + ks) * 32 + lane) * 2;
                const float2 bh = *(const float2*)(Khs + baseK);
                const float2 bl = *(const float2*)(Kls + baseK);
                const unsigned bh0 = __float_as_uint(bh.x);
                const unsigned bh1 = __float_as_uint(bh.y);
                const unsigned bl0 = __float_as_uint(bl.x);
                const unsigned bl1 = __float_as_uint(bl.y);
                #pragma unroll
                for (int mi = 0; mi < 2; mi++) {
                    mma_tf32(sc[mi][nd], aqh[mi][ks], bh0, bh1);
                    mma_tf32(sc[mi][nd], aqh[mi][ks], bl0, bl1);
                    mma_tf32(sc[mi][nd], aql[mi][ks], bh0, bh1);
                }
            }
        }

        // ---- online softmax (exp2 domain) ----
        #pragma unroll
        for (int mi = 0; mi < 2; mi++) {
            float t0 = -1e30f, t1 = -1e30f;
            #pragma unroll
            for (int nd = 0; nd < 4; nd++) {
                t0 = fmaxf(t0, fmaxf(sc[mi][nd][0], sc[mi][nd][1]));
                t1 = fmaxf(t1, fmaxf(sc[mi][nd][2], sc[mi][nd][3]));
            }
            t0 = fmaxf(t0, __shfl_xor_sync(0xffffffffu, t0, 1));
            t0 = fmaxf(t0, __shfl_xor_sync(0xffffffffu, t0, 2));
            t1 = fmaxf(t1, __shfl_xor_sync(0xffffffffu, t1, 1));
            t1 = fmaxf(t1, __shfl_xor_sync(0xffffffffu, t1, 2));

            const float nm0 = fmaxf(m[mi][0], t0);
            const float nm1 = fmaxf(m[mi][1], t1);
            const float c0  = exp2f(m[mi][0] - nm0);
            const float c1  = exp2f(m[mi][1] - nm1);

            float rs0 = 0.f, rs1 = 0.f;
            #pragma unroll
            for (int nd = 0; nd < 4; nd++) {
                sc[mi][nd][0] = exp2f(sc[mi][nd][0] - nm0);
                sc[mi][nd][1] = exp2f(sc[mi][nd][1] - nm0);
                sc[mi][nd][2] = exp2f(sc[mi][nd][2] - nm1);
                sc[mi][nd][3] = exp2f(sc[mi][nd][3] - nm1);
                rs0 += sc[mi][nd][0] + sc[mi][nd][1];
                rs1 += sc[mi][nd][2] + sc[mi][nd][3];
            }
            rs0 += __shfl_xor_sync(0xffffffffu, rs0, 1);
            rs0 += __shfl_xor_sync(0xffffffffu, rs0, 2);
            rs1 += __shfl_xor_sync(0xffffffffu, rs1, 1);
            rs1 += __shfl_xor_sync(0xffffffffu, rs1, 2);

            l[mi][0] = l[mi][0] * c0 + rs0;
            l[mi][1] = l[mi][1] * c1 + rs1;
            #pragma unroll
            for (int nd = 0; nd < 4; nd++) {
                o[mi][nd][0] *= c0; o[mi][nd][1] *= c0;
                o[mi][nd][2] *= c1; o[mi][nd][3] *= c1;
            }
            m[mi][0] = nm0;
            m[mi][1] = nm1;
        }

        // ---- PV (single tf32); P C-frag -> A-frag via intra-quad shuffles ----
        const int sA = t >> 1;
        const int sB = sA + 2;
        const bool odd = (t & 1);
        #pragma unroll
        for (int kst = 0; kst < 4; kst++) {
            unsigned ap[2][4];
            #pragma unroll
            for (int mi = 0; mi < 2; mi++) {
                const float p0 = sc[mi][kst][0], p1 = sc[mi][kst][1];
                const float p2 = sc[mi][kst][2], p3 = sc[mi][kst][3];
                const float x0 = __shfl_sync(0xffffffffu, p0, sA, 4);
                const float x1 = __shfl_sync(0xffffffffu, p1, sA, 4);
                const float y0 = __shfl_sync(0xffffffffu, p0, sB, 4);
                const float y1 = __shfl_sync(0xffffffffu, p1, sB, 4);
                const float z0 = __shfl_sync(0xffffffffu, p2, sA, 4);
                const float z1 = __shfl_sync(0xffffffffu, p3, sA, 4);
                const float w0 = __shfl_sync(0xffffffffu, p2, sB, 4);
                const float w1 = __shfl_sync(0xffffffffu, p3, sB, 4);
                ap[mi][0] = f2tf(odd ? x1 : x0);
                ap[mi][1] = f2tf(odd ? z1 : z0);
                ap[mi][2] = f2tf(odd ? y1 : y0);
                ap[mi][3] = f2tf(odd ? w1 : w0);
            }
            #pragma unroll
            for (int nd = 0; nd < 4; nd++) {
                const float2 bv = *(const float2*)(Vvs + ((kst * 4 + nd) * 32 + lane) * 2);
                const unsigned b0 = __float_as_uint(bv.x);
                const unsigned b1 = __float_as_uint(bv.y);
                #pragma unroll
                for (int mi = 0; mi < 2; mi++)
                    mma_tf32(o[mi][nd], ap[mi], b0, b1);
            }
        }
        __syncthreads();
    }

    // ---- epilogue ----
    const int n = nh >> 4;
    #pragma unroll
    for (int mi = 0; mi < 2; mi++) {
        const float i0 = 1.0f / l[mi][0];
        const float i1 = 1.0f / l[mi][1];
        float* op0 = g_O + ((size_t)(q0 + mi * 16 + g)     * NB + n) * EMB + h * HD;
        float* op1 = g_O + ((size_t)(q0 + mi * 16 + g + 8) * NB + n) * EMB + h * HD;
        #pragma unroll
        for (int nd = 0; nd < 4; nd++) {
            const int col = nd * 8 + 2 * t;
            *(float2*)(op0 + col) = make_float2(o[mi][nd][0] * i0, o[mi][nd][1] * i0);
            *(float2*)(op1 + col) = make_float2(o[mi][nd][2] * i1, o[mi][nd][3] * i1);
        }
    }
}

// ---------------------------------------------------------------------------
extern "C" void kernel_launch(void* const* d_in, const int* in_sizes, int n_in,
                              void* d_out, int out_size)
{
    const float* query   = (const float*)d_in[0];
    const float* key_in  = (const float*)d_in[1];
    const float* value   = (const float*)d_in[2];
    const float* scaling = (const float*)d_in[3];
    const float* in_w    = (const float*)d_in[4];
    const float* in_b    = (const float*)d_in[5];
    const float* pn_w    = (const float*)d_in[6];
    const float* pn_b    = (const float*)d_in[7];
    const float* out_w   = (const float*)d_in[8];
    const float* out_b   = (const float*)d_in[9];
    float* out = (float*)d_out;

    // 1) QKV projections -> scratch in [n,h,len,d]
    dim3 gproj(ROWS / 256, EMB / 128, 3);
    gemm_mma_kernel<0><<<gproj, 256>>>(query, key_in, value, in_w, in_b, nullptr);

    // 2) LayerNorm K and V over D
    const int ln_rows = 2 * NB * NH * SK;
    ln_kernel<<<ln_rows / 8, 256>>>(pn_w, pn_b);

    // 3) Flash attention
    dim3 gattn(LQ / 128, NB * NH);
    attn_mma_kernel<<<gattn, 128>>>(scaling);

    // 4) Output projection -> d_out
    dim3 gout(ROWS / 256, EMB / 128, 1);
    gemm_mma_kernel<1><<<gout, 256>>>(nullptr, nullptr, nullptr, out_w, out_b, out);
}

// round 6
// speedup vs baseline: 1.0028x; 1.0028x over previous
#include <cuda_runtime.h>

#define LQ  2048
#define SK  2048
#define NB  4
#define EMB 512
#define NH  16
#define HD  32
#define ROWS (LQ * NB)   // 8192

// Scratch (allocation-free rule: __device__ globals)
__device__ float g_Q[NB * NH * LQ * HD];   // [n,h,l,d]
__device__ float g_K[NB * NH * SK * HD];   // [n,h,s,d]
__device__ float g_V[NB * NH * SK * HD];
__device__ float g_O[ROWS * EMB];          // attention output, (l*NB+n, e) row-major

// ---------------------------------------------------------------------------
// tf32 helpers
// ---------------------------------------------------------------------------
__device__ __forceinline__ unsigned f2tf(float x) {
    unsigned r;
    asm("cvt.rna.tf32.f32 %0, %1;" : "=r"(r) : "f"(x));
    return r;
}
__device__ __forceinline__ float tf32f(float x) {
    return __uint_as_float(f2tf(x));
}
__device__ __forceinline__ void mma_tf32(float* c, const unsigned* a,
                                         unsigned b0, unsigned b1) {
    asm volatile(
        "mma.sync.aligned.m16n8k8.row.col.f32.tf32.tf32.f32 "
        "{%0,%1,%2,%3}, {%4,%5,%6,%7}, {%8,%9}, {%0,%1,%2,%3};"
        : "+f"(c[0]), "+f"(c[1]), "+f"(c[2]), "+f"(c[3])
        : "r"(a[0]), "r"(a[1]), "r"(a[2]), "r"(a[3]), "r"(b0), "r"(b1));
}

// ---------------------------------------------------------------------------
// 3xTF32 tensor-core GEMM: out[r,f] = sum_e A[r,e] * W[f,e] + bias[f]
// Block tile 256x128, BK=16, 256 threads = 8 warps (4 along M x 2 along N),
// warptile 64x64 (mi=4, ni=8). Smem holds hi/lo tiles in a permuted
// fragment-native layout: a-frags load as one LDS.128, b-frags as LDS.64.
// ---------------------------------------------------------------------------
template<int MODE>
__global__ __launch_bounds__(256)
void gemm_mma_kernel(const float* __restrict__ Aq, const float* __restrict__ Ak,
                     const float* __restrict__ Av, const float* __restrict__ Wfull,
                     const float* __restrict__ bfull, float* __restrict__ outp)
{
    // A: 16 m-groups x 2 kb x 32 lanes x float4  = 4096 floats (16KB) each
    // B:  16 n-groups x 2 kb x 32 lanes x float2 = 2048 floats (8KB)  each
    __shared__ float Ah_s[4096];
    __shared__ float Al_s[4096];
    __shared__ float Bh_s[2048];
    __shared__ float Bl_s[2048];

    const int tid    = threadIdx.x;
    const int warp   = tid >> 5;
    const int lane   = tid & 31;
    const int g      = lane >> 2;
    const int t      = lane & 3;
    const int warp_m = warp >> 1;   // 0..3
    const int warp_n = warp & 1;    // 0..1
    const int r0     = blockIdx.x * 256;
    const int f0     = blockIdx.y * 128;

    const float* A;
    const float* W;
    const float* bias;
    if (MODE == 0) {
        const int z = blockIdx.z;
        A    = (z == 0) ? Aq : (z == 1) ? Ak : Av;
        W    = Wfull + z * EMB * EMB;
        bias = bfull + z * EMB;
    } else {
        A    = g_O;
        W    = Wfull;
        bias = bfull;
    }

    const int rowBase = tid >> 2;          // 0..63
    const int kkL     = (tid & 3) << 2;    // 0,4,8,12

    float acc[4][8][4];
    #pragma unroll
    for (int mi = 0; mi < 4; mi++)
        #pragma unroll
        for (int ni = 0; ni < 8; ni++)
            #pragma unroll
            for (int j = 0; j < 4; j++) acc[mi][ni][j] = 0.f;

    // initial global prefetch
    float4 aReg[4], bReg[2];
    #pragma unroll
    for (int i = 0; i < 4; i++)
        aReg[i] = *(const float4*)(A + (size_t)(r0 + rowBase + i * 64) * EMB + kkL);
    #pragma unroll
    for (int i = 0; i < 2; i++)
        bReg[i] = *(const float4*)(W + (size_t)(f0 + rowBase + i * 64) * EMB + kkL);

    for (int k0 = 0; k0 < EMB; k0 += 16) {
        // ---- store prefetched tile to smem (permuted, hi/lo split) ----
        #pragma unroll
        for (int i = 0; i < 4; i++) {
            const int r  = rowBase + i * 64;
            const int mt = r >> 4;
            const int gg = r & 15;
            const float x[4] = {aReg[i].x, aReg[i].y, aReg[i].z, aReg[i].w};
            #pragma unroll
            for (int j = 0; j < 4; j++) {
                const int c  = kkL + j;
                const int kb = c >> 3;
                const int cc = c & 7;
                const int off = (((mt * 2 + kb) * 32) + ((gg & 7) * 4 + (cc & 3))) * 4
                                + ((cc >> 2) * 2 + (gg >> 3));
                const float h = tf32f(x[j]);
                Ah_s[off] = h;
                Al_s[off] = tf32f(x[j] - h);
            }
        }
        #pragma unroll
        for (int i = 0; i < 2; i++) {
            const int n  = rowBase + i * 64;
            const int nt = n >> 3;
            const int gb = n & 7;
            const float x[4] = {bReg[i].x, bReg[i].y, bReg[i].z, bReg[i].w};
            #pragma unroll
            for (int j = 0; j < 4; j++) {
                const int c  = kkL + j;
                const int kb = c >> 3;
                const int cc = c & 7;
                const int off = (((nt * 2 + kb) * 32) + (gb * 4 + (cc & 3))) * 2
                                + (cc >> 2);
                const float h = tf32f(x[j]);
                Bh_s[off] = h;
                Bl_s[off] = tf32f(x[j] - h);
            }
        }
        __syncthreads();

        // ---- issue next global loads (overlap with compute) ----
        if (k0 + 16 < EMB) {
            #pragma unroll
            for (int i = 0; i < 4; i++)
                aReg[i] = *(const float4*)(A + (size_t)(r0 + rowBase + i * 64) * EMB + k0 + 16 + kkL);
            #pragma unroll
            for (int i = 0; i < 2; i++)
                bReg[i] = *(const float4*)(W + (size_t)(f0 + rowBase + i * 64) * EMB + k0 + 16 + kkL);
        }

        // ---- compute ----
        #pragma unroll
        for (int kb = 0; kb < 2; kb++) {
            unsigned ah[4][4], al[4][4];
            #pragma unroll
            for (int mi = 0; mi < 4; mi++) {
                const int base = (((warp_m * 4 + mi) * 2 + kb) * 32 + lane) * 4;
                const float4 fh = *(const float4*)(Ah_s + base);
                const float4 fl = *(const float4*)(Al_s + base);
                ah[mi][0] = __float_as_uint(fh.x);
                ah[mi][1] = __float_as_uint(fh.y);
                ah[mi][2] = __float_as_uint(fh.z);
                ah[mi][3] = __float_as_uint(fh.w);
                al[mi][0] = __float_as_uint(fl.x);
                al[mi][1] = __float_as_uint(fl.y);
                al[mi][2] = __float_as_uint(fl.z);
                al[mi][3] = __float_as_uint(fl.w);
            }
            #pragma unroll
            for (int ni = 0; ni < 8; ni++) {
                const int baseB = (((warp_n * 8 + ni) * 2 + kb) * 32 + lane) * 2;
                const float2 bh = *(const float2*)(Bh_s + baseB);
                const float2 bl = *(const float2*)(Bl_s + baseB);
                const unsigned bh0 = __float_as_uint(bh.x);
                const unsigned bh1 = __float_as_uint(bh.y);
                const unsigned bl0 = __float_as_uint(bl.x);
                const unsigned bl1 = __float_as_uint(bl.y);
                #pragma unroll
                for (int mi = 0; mi < 4; mi++) {
                    mma_tf32(acc[mi][ni], ah[mi], bh0, bh1);
                    mma_tf32(acc[mi][ni], ah[mi], bl0, bl1);
                    mma_tf32(acc[mi][ni], al[mi], bh0, bh1);
                }
            }
        }
        __syncthreads();
    }

    // ---- epilogue: c0=(g,2t) c1=(g,2t+1) c2=(g+8,2t) c3=(g+8,2t+1) ----
    #pragma unroll
    for (int mi = 0; mi < 4; mi++) {
        const int rA = r0 + warp_m * 64 + mi * 16 + g;
        const int rB = rA + 8;
        #pragma unroll
        for (int ni = 0; ni < 8; ni++) {
            const float* c = acc[mi][ni];
            const int f  = f0 + warp_n * 64 + ni * 8 + 2 * t;
            const float b0 = bias[f];
            const float b1 = bias[f + 1];
            if (MODE == 0) {
                float* dst = (blockIdx.z == 0) ? g_Q : (blockIdx.z == 1) ? g_K : g_V;
                const int h = f >> 5;
                const int d = f & 31;
                {
                    const int l = rA >> 2, n = rA & 3;
                    *(float2*)(dst + ((size_t)(n * NH + h) * LQ + l) * HD + d) =
                        make_float2(c[0] + b0, c[1] + b1);
                }
                {
                    const int l = rB >> 2, n = rB & 3;
                    *(float2*)(dst + ((size_t)(n * NH + h) * LQ + l) * HD + d) =
                        make_float2(c[2] + b0, c[3] + b1);
                }
            } else {
                *(float2*)(outp + (size_t)rA * EMB + f) = make_float2(c[0] + b0, c[1] + b1);
                *(float2*)(outp + (size_t)rB * EMB + f) = make_float2(c[2] + b0, c[3] + b1);
            }
        }
    }
}

// ---------------------------------------------------------------------------
// LayerNorm over D=32 for K and V (one warp per row)
// ---------------------------------------------------------------------------
__global__ __launch_bounds__(256)
void ln_kernel(const float* __restrict__ w, const float* __restrict__ b)
{
    const int gw   = (blockIdx.x * blockDim.x + threadIdx.x) >> 5;
    const int lane = threadIdx.x & 31;
    const int R    = NB * NH * SK;
    if (gw >= 2 * R) return;
    float* X      = (gw < R) ? g_K : g_V;
    const int row = (gw < R) ? gw : gw - R;

    float x = X[(size_t)row * HD + lane];
    float s = x;
    #pragma unroll
    for (int o = 16; o; o >>= 1) s += __shfl_xor_sync(0xffffffffu, s, o);
    const float mu = s * (1.0f / HD);
    const float dv = x - mu;
    float vv = dv * dv;
    #pragma unroll
    for (int o = 16; o; o >>= 1) vv += __shfl_xor_sync(0xffffffffu, vv, o);
    const float inv = rsqrtf(vv * (1.0f / HD) + 1e-5f);
    X[(size_t)row * HD + lane] = dv * inv * w[lane] + b[lane];
}

// ---------------------------------------------------------------------------
// Flash attention, tf32 mma.sync, 3xTF32-compensated QK, single-tf32 PV.
// Block 128 thr (4 warps); each warp 32 q rows (mi=2); block = 128 q rows.
// S-chunks of 32; K (hi/lo) and V stored in fragment-native permuted smem.
// Q pre-scaled by beta*log2(e); softmax in exp2 domain.
// ---------------------------------------------------------------------------
__global__ __launch_bounds__(128)
void attn_mma_kernel(const float* __restrict__ scaling)
{
    __shared__ float Khs[1024];   // [(nd*4+ks)*32+lane]*2+comp
    __shared__ float Kls[1024];
    __shared__ float Vvs[1024];   // [(kst*4+nd)*32+lane]*2+comp

    const int tid  = threadIdx.x;
    const int warp = tid >> 5;
    const int lane = tid & 31;
    const int g    = lane >> 2;
    const int t    = lane & 3;
    const int nh   = blockIdx.y;   // n*NH + h
    const int h    = nh & (NH - 1);
    const float betaL = scaling[h] * 1.4426950408889634f;
    const int q0   = blockIdx.x * 128 + warp * 32;

    // Q fragments: rows q0 + mi*16 + {g, g+8}, cols ks*8 + {t, t+4}; hi/lo split
    const float* Qp = g_Q + ((size_t)nh * LQ + q0) * HD;
    unsigned aqh[2][4][4], aql[2][4][4];
    #pragma unroll
    for (int mi = 0; mi < 2; mi++) {
        #pragma unroll
        for (int ks = 0; ks < 4; ks++) {
            const float q00 = Qp[(size_t)(mi * 16 + g)     * HD + ks * 8 + t]     * betaL;
            const float q10 = Qp[(size_t)(mi * 16 + g + 8) * HD + ks * 8 + t]     * betaL;
            const float q01 = Qp[(size_t)(mi * 16 + g)     * HD + ks * 8 + t + 4] * betaL;
            const float q11 = Qp[(size_t)(mi * 16 + g + 8) * HD + ks * 8 + t + 4] * betaL;
            aqh[mi][ks][0] = f2tf(q00);
            aqh[mi][ks][1] = f2tf(q10);
            aqh[mi][ks][2] = f2tf(q01);
            aqh[mi][ks][3] = f2tf(q11);
            aql[mi][ks][0] = f2tf(q00 - __uint_as_float(aqh[mi][ks][0]));
            aql[mi][ks][1] = f2tf(q10 - __uint_as_float(aqh[mi][ks][1]));
            aql[mi][ks][2] = f2tf(q01 - __uint_as_float(aqh[mi][ks][2]));
            aql[mi][ks][3] = f2tf(q11 - __uint_as_float(aqh[mi][ks][3]));
        }
    }

    float m[2][2], l[2][2], o[2][4][4];
    #pragma unroll
    for (int mi = 0; mi < 2; mi++) {
        m[mi][0] = m[mi][1] = -1e30f;
        l[mi][0] = l[mi][1] = 0.f;
        #pragma unroll
        for (int nd = 0; nd < 4; nd++)
            #pragma unroll
            for (int j = 0; j < 4; j++) o[mi][nd][j] = 0.f;
    }

    const float* Kb = g_K + (size_t)nh * SK * HD;
    const float* Vb = g_V + (size_t)nh * SK * HD;
    const int sRow = tid >> 3;          // 0..15
    const int dCol = (tid & 7) << 2;    // 0,4,...,28

    for (int s0 = 0; s0 < SK; s0 += 32) {
        // ---- cooperative load: 32x32 K (hi/lo) + V into permuted smem ----
        #pragma unroll
        for (int i = 0; i < 2; i++) {
            const int s = sRow + i * 16;
            const int ndK = s >> 3, gK = s & 7;
            const float4 kv = *(const float4*)(Kb + (size_t)(s0 + s) * HD + dCol);
            const float kx[4] = {kv.x, kv.y, kv.z, kv.w};
            #pragma unroll
            for (int j = 0; j < 4; j++) {
                const int d = dCol + j;
                const int ks_ = d >> 3, cc = d & 7;
                const int off = ((ndK * 4 + ks_) * 32 + gK * 4 + (cc & 3)) * 2 + (cc >> 2);
                const float hh = tf32f(kx[j]);
                Khs[off] = hh;
                Kls[off] = tf32f(kx[j] - hh);
            }
            const int kstV = s >> 3, ssV = s & 7;
            const int tV = ssV & 3, compV = ssV >> 2;
            const float4 vv = *(const float4*)(Vb + (size_t)(s0 + s) * HD + dCol);
            const float vx[4] = {vv.x, vv.y, vv.z, vv.w};
            #pragma unroll
            for (int j = 0; j < 4; j++) {
                const int d = dCol + j;
                const int ndV = d >> 3, gV = d & 7;
                Vvs[((kstV * 4 + ndV) * 32 + gV * 4 + tV) * 2 + compV] = tf32f(vx[j]);
            }
        }
        __syncthreads();

        // ---- QK scores (3xTF32) ----
        float sc[2][4][4];
        #pragma unroll
        for (int mi = 0; mi < 2; mi++)
            #pragma unroll
            for (int nd = 0; nd < 4; nd++)
                #pragma unroll
                for (int j = 0; j < 4; j++) sc[mi][nd][j] = 0.f;

        #pragma unroll
        for (int nd = 0; nd < 4; nd++) {
            #pragma unroll
            for (int ks = 0; ks < 4; ks++) {
                const int baseK = ((nd * 4 + ks) * 32 + lane) * 2;
                const float2 bh = *(const float2*)(Khs + baseK);
                const float2 bl = *(const float2*)(Kls + baseK);
                const unsigned bh0 = __float_as_uint(bh.x);
                const unsigned bh1 = __float_as_uint(bh.y);
                const unsigned bl0 = __float_as_uint(bl.x);
                const unsigned bl1 = __float_as_uint(bl.y);
                #pragma unroll
                for (int mi = 0; mi < 2; mi++) {
                    mma_tf32(sc[mi][nd], aqh[mi][ks], bh0, bh1);
                    mma_tf32(sc[mi][nd], aqh[mi][ks], bl0, bl1);
                    mma_tf32(sc[mi][nd], aql[mi][ks], bh0, bh1);
                }
            }
        }

        // ---- online softmax (exp2 domain) ----
        #pragma unroll
        for (int mi = 0; mi < 2; mi++) {
            float t0 = -1e30f, t1 = -1e30f;
            #pragma unroll
            for (int nd = 0; nd < 4; nd++) {
                t0 = fmaxf(t0, fmaxf(sc[mi][nd][0], sc[mi][nd][1]));
                t1 = fmaxf(t1, fmaxf(sc[mi][nd][2], sc[mi][nd][3]));
            }
            t0 = fmaxf(t0, __shfl_xor_sync(0xffffffffu, t0, 1));
            t0 = fmaxf(t0, __shfl_xor_sync(0xffffffffu, t0, 2));
            t1 = fmaxf(t1, __shfl_xor_sync(0xffffffffu, t1, 1));
            t1 = fmaxf(t1, __shfl_xor_sync(0xffffffffu, t1, 2));

            const float nm0 = fmaxf(m[mi][0], t0);
            const float nm1 = fmaxf(m[mi][1], t1);
            const float c0  = exp2f(m[mi][0] - nm0);
            const float c1  = exp2f(m[mi][1] - nm1);

            float rs0 = 0.f, rs1 = 0.f;
            #pragma unroll
            for (int nd = 0; nd < 4; nd++) {
                sc[mi][nd][0] = exp2f(sc[mi][nd][0] - nm0);
                sc[mi][nd][1] = exp2f(sc[mi][nd][1] - nm0);
                sc[mi][nd][2] = exp2f(sc[mi][nd][2] - nm1);
                sc[mi][nd][3] = exp2f(sc[mi][nd][3] - nm1);
                rs0 += sc[mi][nd][0] + sc[mi][nd][1];
                rs1 += sc[mi][nd][2] + sc[mi][nd][3];
            }
            rs0 += __shfl_xor_sync(0xffffffffu, rs0, 1);
            rs0 += __shfl_xor_sync(0xffffffffu, rs0, 2);
            rs1 += __shfl_xor_sync(0xffffffffu, rs1, 1);
            rs1 += __shfl_xor_sync(0xffffffffu, rs1, 2);

            l[mi][0] = l[mi][0] * c0 + rs0;
            l[mi][1] = l[mi][1] * c1 + rs1;
            #pragma unroll
            for (int nd = 0; nd < 4; nd++) {
                o[mi][nd][0] *= c0; o[mi][nd][1] *= c0;
                o[mi][nd][2] *= c1; o[mi][nd][3] *= c1;
            }
            m[mi][0] = nm0;
            m[mi][1] = nm1;
        }

        // ---- PV (single tf32); P C-frag -> A-frag via intra-quad shuffles ----
        const int sA = t >> 1;
        const int sB = sA + 2;
        const bool odd = (t & 1);
        #pragma unroll
        for (int kst = 0; kst < 4; kst++) {
            unsigned ap[2][4];
            #pragma unroll
            for (int mi = 0; mi < 2; mi++) {
                const float p0 = sc[mi][kst][0], p1 = sc[mi][kst][1];
                const float p2 = sc[mi][kst][2], p3 = sc[mi][kst][3];
                const float x0 = __shfl_sync(0xffffffffu, p0, sA, 4);
                const float x1 = __shfl_sync(0xffffffffu, p1, sA, 4);
                const float y0 = __shfl_sync(0xffffffffu, p0, sB, 4);
                const float y1 = __shfl_sync(0xffffffffu, p1, sB, 4);
                const float z0 = __shfl_sync(0xffffffffu, p2, sA, 4);
                const float z1 = __shfl_sync(0xffffffffu, p3, sA, 4);
                const float w0 = __shfl_sync(0xffffffffu, p2, sB, 4);
                const float w1 = __shfl_sync(0xffffffffu, p3, sB, 4);
                ap[mi][0] = f2tf(odd ? x1 : x0);
                ap[mi][1] = f2tf(odd ? z1 : z0);
                ap[mi][2] = f2tf(odd ? y1 : y0);
                ap[mi][3] = f2tf(odd ? w1 : w0);
            }
            #pragma unroll
            for (int nd = 0; nd < 4; nd++) {
                const float2 bv = *(const float2*)(Vvs + ((kst * 4 + nd) * 32 + lane) * 2);
                const unsigned b0 = __float_as_uint(bv.x);
                const unsigned b1 = __float_as_uint(bv.y);
                #pragma unroll
                for (int mi = 0; mi < 2; mi++)
                    mma_tf32(o[mi][nd], ap[mi], b0, b1);
            }
        }
        __syncthreads();
    }

    // ---- epilogue ----
    const int n = nh >> 4;
    #pragma unroll
    for (int mi = 0; mi < 2; mi++) {
        const float i0 = 1.0f / l[mi][0];
        const float i1 = 1.0f / l[mi][1];
        float* op0 = g_O + ((size_t)(q0 + mi * 16 + g)     * NB + n) * EMB + h * HD;
        float* op1 = g_O + ((size_t)(q0 + mi * 16 + g + 8) * NB + n) * EMB + h * HD;
        #pragma unroll
        for (int nd = 0; nd < 4; nd++) {
            const int col = nd * 8 + 2 * t;
            *(float2*)(op0 + col) = make_float2(o[mi][nd][0] * i0, o[mi][nd][1] * i0);
            *(float2*)(op1 + col) = make_float2(o[mi][nd][2] * i1, o[mi][nd][3] * i1);
        }
    }
}

// ---------------------------------------------------------------------------
extern "C" void kernel_launch(void* const* d_in, const int* in_sizes, int n_in,
                              void* d_out, int out_size)
{
    const float* query   = (const float*)d_in[0];
    const float* key_in  = (const float*)d_in[1];
    const float* value   = (const float*)d_in[2];
    const float* scaling = (const float*)d_in[3];
    const float* in_w    = (const float*)d_in[4];
    const float* in_b    = (const float*)d_in[5];
    const float* pn_w    = (const float*)d_in[6];
    const float* pn_b    = (const float*)d_in[7];
    const float* out_w   = (const float*)d_in[8];
    const float* out_b   = (const float*)d_in[9];
    float* out = (float*)d_out;

    // 1) QKV projections -> scratch in [n,h,len,d]
    dim3 gproj(ROWS / 256, EMB / 128, 3);
    gemm_mma_kernel<0><<<gproj, 256>>>(query, key_in, value, in_w, in_b, nullptr);

    // 2) LayerNorm K and V over D
    const int ln_rows = 2 * NB * NH * SK;
    ln_kernel<<<ln_rows / 8, 256>>>(pn_w, pn_b);

    // 3) Flash attention
    dim3 gattn(LQ / 128, NB * NH);
    attn_mma_kernel<<<gattn, 128>>>(scaling);

    // 4) Output projection -> d_out
    dim3 gout(ROWS / 256, EMB / 128, 1);
    gemm_mma_kernel<1><<<gout, 256>>>(nullptr, nullptr, nullptr, out_w, out_b, out);
}